// round 3
// baseline (speedup 1.0000x reference)
#include <cuda_runtime.h>
#include <cuda_fp16.h>
#include <cstdint>

#define H_  32
#define SQ_ 2048
#define SK_ 2048
#define DH_ 128
#define QT  128          // q rows per CTA
#define KT  64           // k per cp.async chunk
#define NCH (SK_/KT)     // 32 chunks
#define NKS (SK_/16)     // 128 ksteps

// V converted to fp16, natural [h][k][d] layout
__device__ alignas(16) __half g_vh[(size_t)H_ * SK_ * DH_];

__device__ __forceinline__ uint32_t smem_u32(const void* p) {
    uint32_t a;
    asm("{ .reg .u64 t; cvta.to.shared.u64 t, %1; cvt.u32.u64 %0, t; }" : "=r"(a) : "l"(p));
    return a;
}

#define MMA16816(D, A, B0, B1) \
    asm volatile( \
        "mma.sync.aligned.m16n8k16.row.col.f32.f16.f16.f32 " \
        "{%0,%1,%2,%3}, {%4,%5,%6,%7}, {%8,%9}, {%0,%1,%2,%3};" \
        : "+f"((D)[0]), "+f"((D)[1]), "+f"((D)[2]), "+f"((D)[3]) \
        : "r"((A)[0]), "r"((A)[1]), "r"((A)[2]), "r"((A)[3]), \
          "r"(B0), "r"(B1))

// ---------------- V fp32 -> fp16 convert ----------------
__global__ void convert_v_kernel(const float* __restrict__ v) {
    size_t i = ((size_t)blockIdx.x * 256 + threadIdx.x) * 8;
    float4 a = *(const float4*)(v + i);
    float4 b = *(const float4*)(v + i + 4);
    __half2 h0 = __floats2half2_rn(a.x, a.y);
    __half2 h1 = __floats2half2_rn(a.z, a.w);
    __half2 h2 = __floats2half2_rn(b.x, b.y);
    __half2 h3 = __floats2half2_rn(b.z, b.w);
    uint4 o;
    o.x = *(uint32_t*)&h0; o.y = *(uint32_t*)&h1;
    o.z = *(uint32_t*)&h2; o.w = *(uint32_t*)&h3;
    *(uint4*)(g_vh + i) = o;
}

// ---------------- Main fused kernel ----------------
// CTA: 128 threads = 4 warps. Warp w handles q rows [32w, 32w+32), all n=128.
// Accum: 2 mtiles x 16 ntiles x 4 = 128 fp32 regs per lane.
__global__ void __launch_bounds__(128)
attn_sink_kernel(const float* __restrict__ logits,
                 const float* __restrict__ sinks,
                 float* __restrict__ out)
{
    __shared__ __align__(128) char vsm[2][16384];   // V stages: 64k x 128d fp16, swizzled
    __shared__ float rowsum[QT];

    const int tid = threadIdx.x;
    const int w   = tid >> 5;
    const int l   = tid & 31;
    const int h   = blockIdx.x >> 4;
    const int q0  = (blockIdx.x & 15) * QT;

    const float*  Lbase = logits + ((size_t)h * SQ_ + q0 + w * 32) * SK_;
    const __half* Vh    = g_vh + (size_t)h * SK_ * DH_;
    const uint32_t vb   = smem_u32(vsm);

    // L load pattern: inst i (0..3): lane l -> row 8i + (l>>2), cols 4*(l&3) + 16*gk .. +3
    const float* Lr[4];
#pragma unroll
    for (int i = 0; i < 4; i++)
        Lr[i] = Lbase + (size_t)(8 * i + (l >> 2)) * SK_ + 4 * (l & 3);

    // ldmatrix lane geometry (x4.trans): lanes 0-7 M0(k0-7,n0), 8-15 M1(k8-15,n0),
    // 16-23 M2(k0-7,n0+8), 24-31 M3(k8-15,n0+8)
    const int lu = l >> 4;                       // n +8 select
    const int kl = (l & 7) + 8 * ((l >> 3) & 1); // k row within kstep
    // shuffle source for A frags: s = (l & ~3) | (b<<1) | ((l&3)>>1)
    const int s0  = (l & 28) | ((l & 3) >> 1);
    const bool odd = l & 1;

    float acc[2][16][4];
#pragma unroll
    for (int m = 0; m < 2; m++)
#pragma unroll
        for (int nt = 0; nt < 16; nt++)
#pragma unroll
            for (int c = 0; c < 4; c++) acc[m][nt][c] = 0.f;

    float psum[4] = {0.f, 0.f, 0.f, 0.f};

    // prologue: cp.async chunk 0 -> stage 0
    {
#pragma unroll
        for (int u = 0; u < 8; u++) {
            int c = u * 128 + tid;
            int k = c >> 4, d = (c & 15) * 8;
            uint32_t dst = vb + (uint32_t)((d >> 6) << 13) + (uint32_t)(k << 7)
                         + (uint32_t)((((d >> 3) & 7) ^ (k & 7)) << 4);
            const __half* src = Vh + (size_t)k * DH_ + d;
            asm volatile("cp.async.cg.shared.global [%0], [%1], 16;" :: "r"(dst), "l"(src));
        }
        asm volatile("cp.async.commit_group;");
    }

    // prefetch first kstep of L
    float4 lv[4];
#pragma unroll
    for (int i = 0; i < 4; i++) lv[i] = *(const float4*)(Lr[i]);

    for (int ch = 0; ch < NCH; ch++) {
        __syncthreads();                         // stage (ch+1)&1 free to overwrite
        if (ch + 1 < NCH) {
            int s = (ch + 1) & 1;
#pragma unroll
            for (int u = 0; u < 8; u++) {
                int c = u * 128 + tid;
                int k = c >> 4, d = (c & 15) * 8;
                uint32_t dst = vb + (uint32_t)(s * 16384) + (uint32_t)((d >> 6) << 13)
                             + (uint32_t)(k << 7)
                             + (uint32_t)((((d >> 3) & 7) ^ (k & 7)) << 4);
                const __half* src = Vh + (size_t)((ch + 1) * KT + k) * DH_ + d;
                asm volatile("cp.async.cg.shared.global [%0], [%1], 16;" :: "r"(dst), "l"(src));
            }
        }
        asm volatile("cp.async.commit_group;");
        asm volatile("cp.async.wait_group 1;");  // chunk ch resident
        __syncthreads();

        const uint32_t vstage = vb + (uint32_t)((ch & 1) * 16384);

#pragma unroll
        for (int j = 0; j < 4; j++) {
            const int gk = ch * 4 + j;

            // prefetch next kstep L
            float4 nv[4];
            if (gk < NKS - 1) {
#pragma unroll
                for (int i = 0; i < 4; i++)
                    nv[i] = *(const float4*)(Lr[i] + (size_t)(gk + 1) * 16);
            } else {
#pragma unroll
                for (int i = 0; i < 4; i++) nv[i] = lv[i];
            }

            // exp + rowsum + pack fp16
            uint32_t h2v[4][2];
#pragma unroll
            for (int i = 0; i < 4; i++) {
                float e0 = __expf(lv[i].x), e1 = __expf(lv[i].y);
                float e2 = __expf(lv[i].z), e3 = __expf(lv[i].w);
                psum[i] += (e0 + e1) + (e2 + e3);
                __half2 p0 = __floats2half2_rn(e0, e1);
                __half2 p1 = __floats2half2_rn(e2, e3);
                h2v[i][0] = *(uint32_t*)&p0;
                h2v[i][1] = *(uint32_t*)&p1;
            }

            // form A fragments via shuffles:
            // frag reg (m, a, b): row = 16m+8a+g (g=l>>2), k = 16j+8b+2d (d=l&3)
            // src lane = (l&~3)|(b<<1)|((l&3)>>1); src reg h2v[2m+a][(k>>1)&1 = l&1]
            uint32_t af[2][4];
#pragma unroll
            for (int m = 0; m < 2; m++)
#pragma unroll
                for (int a = 0; a < 2; a++)
#pragma unroll
                    for (int b = 0; b < 2; b++) {
                        uint32_t lo = __shfl_sync(0xffffffffu, h2v[2 * m + a][0], s0 + 2 * b);
                        uint32_t hi = __shfl_sync(0xffffffffu, h2v[2 * m + a][1], s0 + 2 * b);
                        af[m][a + 2 * b] = odd ? hi : lo;
                    }

            const uint32_t rowoff = (uint32_t)((16 * j + kl) << 7);
#pragma unroll
            for (int nt = 0; nt < 16; nt += 2) {
                int u = nt + lu;
                uint32_t addr = vstage + (uint32_t)((u >> 3) << 13) + rowoff
                              + (uint32_t)(((u & 7) ^ (l & 7)) << 4);
                uint32_t b0, b1, b2, b3;
                asm volatile(
                    "ldmatrix.sync.aligned.m8n8.x4.trans.shared.b16 {%0,%1,%2,%3}, [%4];"
                    : "=r"(b0), "=r"(b1), "=r"(b2), "=r"(b3) : "r"(addr));
                MMA16816(acc[0][nt],     af[0], b0, b1);
                MMA16816(acc[1][nt],     af[1], b0, b1);
                MMA16816(acc[0][nt + 1], af[0], b2, b3);
                MMA16816(acc[1][nt + 1], af[1], b2, b3);
            }

#pragma unroll
            for (int i = 0; i < 4; i++) lv[i] = nv[i];
        }
    }

    // rowsum reduce: psum[i] covers row 8i + (l>>2); 4 lanes (xor 1,2) share a row
#pragma unroll
    for (int i = 0; i < 4; i++) {
        float v = psum[i];
        v += __shfl_xor_sync(0xffffffffu, v, 1);
        v += __shfl_xor_sync(0xffffffffu, v, 2);
        if ((l & 3) == 0) rowsum[w * 32 + 8 * i + (l >> 2)] = v;
    }
    __syncthreads();

    // epilogue: O = acc / (rowsum + exp(sink))
    const float sinkv = __expf(sinks[h]);
#pragma unroll
    for (int m = 0; m < 2; m++)
#pragma unroll
        for (int a = 0; a < 2; a++) {
            int r = w * 32 + 16 * m + 8 * a + (l >> 2);
            float inv = 1.0f / (rowsum[r] + sinkv);
            float* orow = out + ((size_t)h * SQ_ + q0 + r) * DH_ + (l & 3) * 2;
#pragma unroll
            for (int nt = 0; nt < 16; nt++) {
                float2 o;
                o.x = acc[m][nt][2 * a + 0] * inv;
                o.y = acc[m][nt][2 * a + 1] * inv;
                *(float2*)(orow + nt * 8) = o;
            }
        }
}

// ---------------- Launch ----------------
extern "C" void kernel_launch(void* const* d_in, const int* in_sizes, int n_in,
                              void* d_out, int out_size) {
    const float* logits = nullptr;
    const float* value  = nullptr;
    const float* sinks  = nullptr;
    for (int i = 0; i < n_in; i++) {
        if (in_sizes[i] == H_) sinks = (const float*)d_in[i];
        else if (in_sizes[i] == H_ * SQ_ * SK_) logits = (const float*)d_in[i];
        else if (in_sizes[i] == H_ * SK_ * DH_) value = (const float*)d_in[i];
    }
    float* out = (float*)d_out;

    // V fp32 -> fp16 (8 elems/thread)
    convert_v_kernel<<<(H_ * SK_ * DH_) / (256 * 8), 256>>>(value);

    attn_sink_kernel<<<H_ * (SQ_ / QT), 128>>>(logits, sinks, out);
}